// round 16
// baseline (speedup 1.0000x reference)
#include <cuda_runtime.h>
#include <cuda_fp16.h>

#define NMAX 100000
#define EMAX 1600000
#define FULL 0xffffffffu

// ---------------- scratch ----------------
__device__ __align__(16) __half g_h1h[NMAX * 64];
__device__ __align__(16) float g_asrc1[NMAX * 8];
__device__ __align__(16) float g_adst1[NMAX * 8];
__device__ __align__(16) float g_hl1[NMAX * 64];
__device__ __align__(16) __half g_h2h[NMAX * 40];
__device__ __align__(16) float g_asrc2[NMAX];
__device__ __align__(16) float g_adst2[NMAX];
__device__ __align__(16) int   g_deg[NMAX];
__device__ __align__(16) int   g_off[NMAX];
__device__ __align__(16) int   g_cur[NMAX];
__device__ __align__(16) int   g_esrc[EMAX];
__device__ __align__(16) int   g_aux[128];
__device__ int g_is64;

// ---------------- K0 ----------------
__global__ void k_zero_detect(const unsigned int* __restrict__ w, int E, int N) {
    int i = blockIdx.x * blockDim.x + threadIdx.x;
    if (i < N) g_deg[i] = 0;
    if (blockIdx.x == 0) {
        int t = threadIdx.x;
        unsigned int acc = 0;
        int sample = min(2 * E, 4096);
        for (int k = 2 * t + 1; k < sample; k += 2 * blockDim.x) acc |= w[k];
#pragma unroll
        for (int d = 16; d; d >>= 1) acc |= __shfl_xor_sync(FULL, acc, d);
        __shared__ unsigned int s[8];
        if ((t & 31) == 0) s[t >> 5] = acc;
        __syncthreads();
        if (t == 0) {
            unsigned int a = 0;
            for (int k = 0; k < 8; k++) a |= s[k];
            g_is64 = (a == 0) ? 1 : 0;
        }
    }
}

__device__ __forceinline__ int edge_at(const void* base, int pos, int N) {
    int v;
    if (g_is64) v = (int)((const long long*)base)[pos];
    else        v = ((const int*)base)[pos];
    return min(max(v, 0), N - 1);
}

__device__ __forceinline__ void edge4(const void* base, int pos, int N, int* out) {
    if (g_is64) {
        longlong2 a = ((const longlong2*)base)[pos >> 1];
        longlong2 b = ((const longlong2*)base)[(pos >> 1) + 1];
        out[0] = (int)a.x; out[1] = (int)a.y; out[2] = (int)b.x; out[3] = (int)b.y;
    } else {
        int4 v = *(const int4*)((const int*)base + pos);
        out[0] = v.x; out[1] = v.y; out[2] = v.z; out[3] = v.w;
    }
#pragma unroll
    for (int k = 0; k < 4; k++) out[k] = min(max(out[k], 0), N - 1);
}

// ---------------- K1: h1 = x @ W1, 512 threads, thread = 2 nodes x 8 cols ----------------
__global__ void __launch_bounds__(512) k_gemm1(
        const float* __restrict__ x, const float* __restrict__ W1,
        const float* __restrict__ attS, const float* __restrict__ attD, int N) {
    __shared__ __align__(16) float xs[128 * 36];
    __shared__ __align__(16) float ws[32 * 64];
    int t = threadIdx.x;
    int h = t & 7, ng = t >> 3;        // ng in 0..63, rows 2*ng, 2*ng+1
    int n0b = blockIdx.x * 128;

    float acc[2][8];
#pragma unroll
    for (int i = 0; i < 2; i++)
#pragma unroll
        for (int c = 0; c < 8; c++) acc[i][c] = 0.f;

    for (int kc = 0; kc < 128; kc += 32) {
#pragma unroll
        for (int i = 0; i < 2; i++) {
            int idx = t + i * 512;            // 0..1023
            int row = idx >> 3, q = idx & 7;
            int n = n0b + row;
            float4 v = make_float4(0.f, 0.f, 0.f, 0.f);
            if (n < N) v = *(const float4*)(x + n * 128 + kc + q * 4);
            *(float4*)(xs + row * 36 + q * 4) = v;
        }
        if (t < 512) {
            *(float4*)(ws + t * 4) = *(const float4*)(W1 + kc * 64 + t * 4);
        }
        __syncthreads();
#pragma unroll
        for (int kk = 0; kk < 32; kk += 4) {
            float4 xq[2];
#pragma unroll
            for (int i = 0; i < 2; i++)
                xq[i] = *(const float4*)(xs + (ng * 2 + i) * 36 + kk);
#pragma unroll
            for (int q = 0; q < 4; q++) {
                float4 w0 = *(const float4*)(ws + (kk + q) * 64 + h * 8);
                float4 w1 = *(const float4*)(ws + (kk + q) * 64 + h * 8 + 4);
#pragma unroll
                for (int i = 0; i < 2; i++) {
                    float xv = (q == 0) ? xq[i].x : (q == 1) ? xq[i].y
                              : (q == 2) ? xq[i].z : xq[i].w;
                    acc[i][0] += xv * w0.x; acc[i][1] += xv * w0.y;
                    acc[i][2] += xv * w0.z; acc[i][3] += xv * w0.w;
                    acc[i][4] += xv * w1.x; acc[i][5] += xv * w1.y;
                    acc[i][6] += xv * w1.z; acc[i][7] += xv * w1.w;
                }
            }
        }
        __syncthreads();
    }

    float as[8], ad[8];
#pragma unroll
    for (int c = 0; c < 8; c++) { as[c] = attS[h * 8 + c]; ad[c] = attD[h * 8 + c]; }
#pragma unroll
    for (int i = 0; i < 2; i++) {
        int n = n0b + ng * 2 + i;
        if (n < N) {
            float sa = 0.f, sd = 0.f;
#pragma unroll
            for (int c = 0; c < 8; c++) { sa += acc[i][c] * as[c]; sd += acc[i][c] * ad[c]; }
            g_asrc1[n * 8 + h] = sa;
            g_adst1[n * 8 + h] = sd;
            __half2 p[4];
#pragma unroll
            for (int q = 0; q < 4; q++)
                p[q] = __floats2half2_rn(acc[i][2 * q], acc[i][2 * q + 1]);
            *(uint4*)(g_h1h + n * 64 + h * 8) = *(uint4*)p;
        }
    }
}

// ---------------- CSR build ----------------
__global__ void k_count(const void* __restrict__ ei, int E, int N) {
    int base = (blockIdx.x * blockDim.x + threadIdx.x) * 4;
    if (base + 3 < E) {
        int d[4];
        edge4(ei, E + base, N, d);
#pragma unroll
        for (int k = 0; k < 4; k++) atomicAdd(&g_deg[d[k]], 1);
    } else {
        for (int e = base; e < E; e++) atomicAdd(&g_deg[edge_at(ei, E + e, N)], 1);
    }
}

__global__ void k_scan1(int N) {
    __shared__ int wsum[8];
    int t = threadIdx.x;
    int base = blockIdx.x * 1024;
    int lane = t & 31, warp = t >> 5;
    int v[4];
    int s = 0;
#pragma unroll
    for (int i = 0; i < 4; i++) {
        int idx = base + t * 4 + i;
        v[i] = (idx < N) ? g_deg[idx] : 0;
        s += v[i];
    }
    int inc = s;
#pragma unroll
    for (int d = 1; d < 32; d <<= 1) {
        int o = __shfl_up_sync(FULL, inc, d);
        if (lane >= d) inc += o;
    }
    if (lane == 31) wsum[warp] = inc;
    __syncthreads();
    if (warp == 0 && lane < 8) {
        int wv = wsum[lane];
        int winc = wv;
#pragma unroll
        for (int d = 1; d < 8; d <<= 1) {
            int o = __shfl_up_sync(0x000000ffu, winc, d);
            if (lane >= d) winc += o;
        }
        wsum[lane] = winc - wv;
        if (lane == 7) g_aux[blockIdx.x] = winc;
    }
    __syncthreads();
    int excl = wsum[warp] + inc - s;
#pragma unroll
    for (int i = 0; i < 4; i++) {
        int idx = base + t * 4 + i;
        if (idx < N) { g_off[idx] = excl; excl += v[i]; }
    }
}

__global__ void k_scan2(int nb) {
    __shared__ int ws[4];
    int t = threadIdx.x;
    int lane = t & 31, warp = t >> 5;
    int v = (t < nb) ? g_aux[t] : 0;
    int inc = v;
#pragma unroll
    for (int d = 1; d < 32; d <<= 1) {
        int o = __shfl_up_sync(FULL, inc, d);
        if (lane >= d) inc += o;
    }
    if (lane == 31) ws[warp] = inc;
    __syncthreads();
    int add = 0;
    for (int w = 0; w < warp; w++) add += ws[w];
    int excl = add + inc - v;
    if (t < nb) g_aux[t] = excl;
}

__global__ void k_scan3(int N) {
    int i = blockIdx.x * blockDim.x + threadIdx.x;
    if (i < N) {
        int o = g_off[i] + g_aux[i >> 10];
        g_off[i] = o;
        g_cur[i] = o;
    }
}

__global__ void k_scatter(const void* __restrict__ ei, int E, int N) {
    int base = (blockIdx.x * blockDim.x + threadIdx.x) * 4;
    if (base + 3 < E) {
        int d[4], sv[4];
        edge4(ei, E + base, N, d);
        edge4(ei, base, N, sv);
#pragma unroll
        for (int k = 0; k < 4; k++) {
            int pos = atomicAdd(&g_cur[d[k]], 1);
            pos = min(max(pos, 0), E - 1);
            g_esrc[pos] = sv[k];
        }
    } else {
        for (int e = base; e < E; e++) {
            int d = edge_at(ei, E + e, N);
            int pos = atomicAdd(&g_cur[d], 1);
            pos = min(max(pos, 0), E - 1);
            g_esrc[pos] = edge_at(ei, e, N);
        }
    }
}

// ---------------- K3: layer-1 aggregation, MLP-8 gathers ----------------
__global__ void k_agg1(const float* __restrict__ b1, int N) {
    __shared__ __align__(16) float sal[8][8 * 36];
    __shared__ float shs[8][8];
    int lane = threadIdx.x & 31;
    int w = threadIdx.x >> 5;
    int node = blockIdx.x * 8 + w;
    if (node >= N) return;
    int start = g_off[node];
    int cnt = g_deg[node] + 1;

    float ad[8];
    {
        float4 d0 = *(const float4*)(g_adst1 + node * 8);
        float4 d1 = *(const float4*)(g_adst1 + node * 8 + 4);
        ad[0] = d0.x; ad[1] = d0.y; ad[2] = d0.z; ad[3] = d0.w;
        ad[4] = d1.x; ad[5] = d1.y; ad[6] = d1.z; ad[7] = d1.w;
    }

    int ha = lane >> 2;
    float accx = 0.f, accy = 0.f;
    float hs[8];
#pragma unroll
    for (int h = 0; h < 8; h++) hs[h] = 0.f;

    for (int base = 0; base < cnt; base += 32) {
        int m = min(32, cnt - base);
        int j = base + lane;
        int mysrc = 0;
        if (lane < m) {
            mysrc = (j == 0) ? node : g_esrc[start + j - 1];
            float4 a0 = *(const float4*)(g_asrc1 + mysrc * 8);
            float4 a1 = *(const float4*)(g_asrc1 + mysrc * 8 + 4);
            float av[8] = {a0.x, a0.y, a0.z, a0.w, a1.x, a1.y, a1.z, a1.w};
#pragma unroll
            for (int h = 0; h < 8; h++) {
                float e = av[h] + ad[h];
                e = (e > 0.f) ? e : 0.2f * e;
                float ex = __expf(e);
                sal[w][h * 36 + lane] = ex;
                hs[h] += ex;
            }
        }
        __syncwarp();
        int jj = 0;
        for (; jj + 8 <= m; jj += 8) {
            int s0 = __shfl_sync(FULL, mysrc, jj);
            int s1 = __shfl_sync(FULL, mysrc, jj + 1);
            int s2 = __shfl_sync(FULL, mysrc, jj + 2);
            int s3 = __shfl_sync(FULL, mysrc, jj + 3);
            int s4 = __shfl_sync(FULL, mysrc, jj + 4);
            int s5 = __shfl_sync(FULL, mysrc, jj + 5);
            int s6 = __shfl_sync(FULL, mysrc, jj + 6);
            int s7 = __shfl_sync(FULL, mysrc, jj + 7);
            float4 pa = *(const float4*)(&sal[w][ha * 36 + jj]);
            float4 pb = *(const float4*)(&sal[w][ha * 36 + jj + 4]);
            float2 f0 = __half22float2(*(const __half2*)(g_h1h + s0 * 64 + 2 * lane));
            float2 f1 = __half22float2(*(const __half2*)(g_h1h + s1 * 64 + 2 * lane));
            float2 f2 = __half22float2(*(const __half2*)(g_h1h + s2 * 64 + 2 * lane));
            float2 f3 = __half22float2(*(const __half2*)(g_h1h + s3 * 64 + 2 * lane));
            float2 f4 = __half22float2(*(const __half2*)(g_h1h + s4 * 64 + 2 * lane));
            float2 f5 = __half22float2(*(const __half2*)(g_h1h + s5 * 64 + 2 * lane));
            float2 f6 = __half22float2(*(const __half2*)(g_h1h + s6 * 64 + 2 * lane));
            float2 f7 = __half22float2(*(const __half2*)(g_h1h + s7 * 64 + 2 * lane));
            accx += pa.x * f0.x + pa.y * f1.x + pa.z * f2.x + pa.w * f3.x
                  + pb.x * f4.x + pb.y * f5.x + pb.z * f6.x + pb.w * f7.x;
            accy += pa.x * f0.y + pa.y * f1.y + pa.z * f2.y + pa.w * f3.y
                  + pb.x * f4.y + pb.y * f5.y + pb.z * f6.y + pb.w * f7.y;
        }
        for (; jj < m; jj++) {
            int s = __shfl_sync(FULL, mysrc, jj);
            float pa = sal[w][ha * 36 + jj];
            float2 f = __half22float2(*(const __half2*)(g_h1h + s * 64 + 2 * lane));
            accx += pa * f.x;
            accy += pa * f.y;
        }
        __syncwarp();
    }

#pragma unroll
    for (int h = 0; h < 8; h++) {
        float v = hs[h];
#pragma unroll
        for (int d = 16; d; d >>= 1) v += __shfl_xor_sync(FULL, v, d);
        if (lane == 0) shs[w][h] = v;
    }
    __syncwarp();
    float inv = 1.f / shs[w][ha];

    float2 bv = *(const float2*)(b1 + 2 * lane);
    float v0 = accx * inv + bv.x;
    float v1 = accy * inv + bv.y;
    v0 = (v0 > 0.f) ? v0 : (__expf(v0) - 1.f);
    v1 = (v1 > 0.f) ? v1 : (__expf(v1) - 1.f);
    *(float2*)(g_hl1 + node * 64 + 2 * lane) = make_float2(v0, v1);
}

// ---------------- K4: h2 = hl1 @ W2 (+ attention dots) ----------------
__global__ void k_gemm2(const float* __restrict__ W2, const float* __restrict__ attS,
                        const float* __restrict__ attD, int N) {
    __shared__ float xs[128 * 33];
    __shared__ float ws[32 * 40];
    int t = threadIdx.x;
    int cg = t & 7, ng = t >> 3;
    int warp = t >> 5, lane = t & 31;
    int n0b = blockIdx.x * 128;

    float acc[4][5];
#pragma unroll
    for (int i = 0; i < 4; i++)
#pragma unroll
        for (int c = 0; c < 5; c++) acc[i][c] = 0.f;

    for (int kc = 0; kc < 64; kc += 32) {
#pragma unroll
        for (int i = 0; i < 16; i++) {
            int row = warp * 16 + i;
            int n = n0b + row;
            xs[row * 33 + lane] = (n < N) ? g_hl1[n * 64 + kc + lane] : 0.f;
        }
        for (int idx = t; idx < 32 * 40; idx += 256) ws[idx] = W2[kc * 40 + idx];
        __syncthreads();
#pragma unroll
        for (int kk = 0; kk < 32; kk++) {
            float xv[4];
#pragma unroll
            for (int i = 0; i < 4; i++) xv[i] = xs[(ng * 4 + i) * 33 + kk];
            float wv[5];
#pragma unroll
            for (int c = 0; c < 5; c++) wv[c] = ws[kk * 40 + cg * 5 + c];
#pragma unroll
            for (int i = 0; i < 4; i++)
#pragma unroll
                for (int c = 0; c < 5; c++) acc[i][c] += xv[i] * wv[c];
        }
        __syncthreads();
    }

    float as[5], ad[5];
#pragma unroll
    for (int c = 0; c < 5; c++) { as[c] = attS[cg * 5 + c]; ad[c] = attD[cg * 5 + c]; }
#pragma unroll
    for (int i = 0; i < 4; i++) {
        int n = n0b + ng * 4 + i;
        float sa = 0.f, sd = 0.f;
#pragma unroll
        for (int c = 0; c < 5; c++) { sa += acc[i][c] * as[c]; sd += acc[i][c] * ad[c]; }
#pragma unroll
        for (int d = 1; d < 8; d <<= 1) {
            sa += __shfl_xor_sync(FULL, sa, d);
            sd += __shfl_xor_sync(FULL, sd, d);
        }
        if (n < N) {
#pragma unroll
            for (int c = 0; c < 5; c++)
                g_h2h[n * 40 + cg * 5 + c] = __float2half_rn(acc[i][c]);
            if (cg == 0) { g_asrc2[n] = sa; g_adst2[n] = sd; }
        }
    }
}

// ---------------- K5: layer-2 aggregation + log_softmax, MLP-8 ----------------
__global__ void k_agg2(const float* __restrict__ b2, float* __restrict__ out, int N) {
    int lane = threadIdx.x & 31;
    int node = blockIdx.x * 8 + (threadIdx.x >> 5);
    if (node >= N) return;
    int start = g_off[node];
    int cnt = g_deg[node] + 1;
    float adst = g_adst2[node];

    float accx = 0.f, accy = 0.f, ps = 0.f;
    for (int base = 0; base < cnt; base += 32) {
        int m = min(32, cnt - base);
        int j = base + lane;
        int mysrc = 0;
        float myal = 0.f;
        if (lane < m) {
            mysrc = (j == 0) ? node : g_esrc[start + j - 1];
            float e = g_asrc2[mysrc] + adst;
            e = (e > 0.f) ? e : 0.2f * e;
            myal = __expf(e);
            ps += myal;
        }
        int jj = 0;
        for (; jj + 8 <= m; jj += 8) {
            int s0 = __shfl_sync(FULL, mysrc, jj);
            int s1 = __shfl_sync(FULL, mysrc, jj + 1);
            int s2 = __shfl_sync(FULL, mysrc, jj + 2);
            int s3 = __shfl_sync(FULL, mysrc, jj + 3);
            int s4 = __shfl_sync(FULL, mysrc, jj + 4);
            int s5 = __shfl_sync(FULL, mysrc, jj + 5);
            int s6 = __shfl_sync(FULL, mysrc, jj + 6);
            int s7 = __shfl_sync(FULL, mysrc, jj + 7);
            float a0 = __shfl_sync(FULL, myal, jj);
            float a1 = __shfl_sync(FULL, myal, jj + 1);
            float a2 = __shfl_sync(FULL, myal, jj + 2);
            float a3 = __shfl_sync(FULL, myal, jj + 3);
            float a4 = __shfl_sync(FULL, myal, jj + 4);
            float a5 = __shfl_sync(FULL, myal, jj + 5);
            float a6 = __shfl_sync(FULL, myal, jj + 6);
            float a7 = __shfl_sync(FULL, myal, jj + 7);
            if (lane < 20) {
                float2 f0 = __half22float2(*(const __half2*)(g_h2h + s0 * 40 + 2 * lane));
                float2 f1 = __half22float2(*(const __half2*)(g_h2h + s1 * 40 + 2 * lane));
                float2 f2 = __half22float2(*(const __half2*)(g_h2h + s2 * 40 + 2 * lane));
                float2 f3 = __half22float2(*(const __half2*)(g_h2h + s3 * 40 + 2 * lane));
                float2 f4 = __half22float2(*(const __half2*)(g_h2h + s4 * 40 + 2 * lane));
                float2 f5 = __half22float2(*(const __half2*)(g_h2h + s5 * 40 + 2 * lane));
                float2 f6 = __half22float2(*(const __half2*)(g_h2h + s6 * 40 + 2 * lane));
                float2 f7 = __half22float2(*(const __half2*)(g_h2h + s7 * 40 + 2 * lane));
                accx += a0 * f0.x + a1 * f1.x + a2 * f2.x + a3 * f3.x
                      + a4 * f4.x + a5 * f5.x + a6 * f6.x + a7 * f7.x;
                accy += a0 * f0.y + a1 * f1.y + a2 * f2.y + a3 * f3.y
                      + a4 * f4.y + a5 * f5.y + a6 * f6.y + a7 * f7.y;
            }
        }
        for (; jj < m; jj++) {
            int s = __shfl_sync(FULL, mysrc, jj);
            float al = __shfl_sync(FULL, myal, jj);
            if (lane < 20) {
                float2 f = __half22float2(*(const __half2*)(g_h2h + s * 40 + 2 * lane));
                accx += al * f.x;
                accy += al * f.y;
            }
        }
    }
#pragma unroll
    for (int d = 16; d; d >>= 1) ps += __shfl_xor_sync(FULL, ps, d);
    float inv = 1.f / ps;

    float v0 = -1e30f, v1 = -1e30f;
    if (lane < 20) {
        v0 = accx * inv + b2[2 * lane];
        v1 = accy * inv + b2[2 * lane + 1];
    }
    float mx = fmaxf(v0, v1);
#pragma unroll
    for (int d = 16; d; d >>= 1) mx = fmaxf(mx, __shfl_xor_sync(FULL, mx, d));
    float se = (lane < 20) ? (__expf(v0 - mx) + __expf(v1 - mx)) : 0.f;
#pragma unroll
    for (int d = 16; d; d >>= 1) se += __shfl_xor_sync(FULL, se, d);
    float ls = __logf(se) + mx;

    if (lane < 20)
        *(float2*)(out + node * 40 + 2 * lane) = make_float2(v0 - ls, v1 - ls);
}

// ---------------- launch ----------------
// NOTE: k_gemm1 is the 4th launch — the profiler captures the 4th launch.
extern "C" void kernel_launch(void* const* d_in, const int* in_sizes, int n_in,
                              void* d_out, int out_size) {
    const float* x   = (const float*)d_in[0];
    const void*  ei  = d_in[1];
    const float* W1  = (const float*)d_in[2];
    const float* aS1 = (const float*)d_in[3];
    const float* aD1 = (const float*)d_in[4];
    const float* b1  = (const float*)d_in[5];
    const float* W2  = (const float*)d_in[6];
    const float* aS2 = (const float*)d_in[7];
    const float* aD2 = (const float*)d_in[8];
    const float* b2  = (const float*)d_in[9];
    float* out = (float*)d_out;

    int N = in_sizes[0] / 128;
    int E = in_sizes[1] / 2;
    int nb1024 = (N + 1023) / 1024;
    int ebq = (E + 1023) / 1024;

    k_zero_detect<<<(N + 255) / 256, 256>>>((const unsigned int*)ei, E, N);
    k_count<<<ebq, 256>>>(ei, E, N);
    k_scan1<<<nb1024, 256>>>(N);
    k_gemm1<<<(N + 127) / 128, 512>>>(x, W1, aS1, aD1, N);   // 4th launch -> profiled
    k_scan2<<<1, 128>>>(nb1024);
    k_scan3<<<(N + 255) / 256, 256>>>(N);
    k_scatter<<<ebq, 256>>>(ei, E, N);
    k_agg1<<<(N + 7) / 8, 256>>>(b1, N);
    k_gemm2<<<(N + 127) / 128, 256>>>(W2, aS2, aD2, N);
    k_agg2<<<(N + 7) / 8, 256>>>(b2, out, N);
}

// round 17
// speedup vs baseline: 1.3745x; 1.3745x over previous
#include <cuda_runtime.h>
#include <cuda_fp16.h>
#include <mma.h>

using namespace nvcuda;

#define NMAX 100000
#define EMAX 1600000
#define FULL 0xffffffffu

// ---------------- scratch ----------------
__device__ __align__(16) __half g_h1h[NMAX * 64];
__device__ __align__(16) float g_asrc1[NMAX * 8];
__device__ __align__(16) float g_adst1[NMAX * 8];
__device__ __align__(16) float g_hl1[NMAX * 64];
__device__ __align__(16) __half g_h2h[NMAX * 40];
__device__ __align__(16) float g_asrc2[NMAX];
__device__ __align__(16) float g_adst2[NMAX];
__device__ __align__(16) int   g_deg[NMAX];
__device__ __align__(16) int   g_off[NMAX];
__device__ __align__(16) int   g_cur[NMAX];
__device__ __align__(16) int   g_esrc[EMAX];
__device__ __align__(16) int   g_aux[128];
__device__ int g_is64;

// ---------------- K0 ----------------
__global__ void k_zero_detect(const unsigned int* __restrict__ w, int E, int N) {
    int i = blockIdx.x * blockDim.x + threadIdx.x;
    if (i < N) g_deg[i] = 0;
    if (blockIdx.x == 0) {
        int t = threadIdx.x;
        unsigned int acc = 0;
        int sample = min(2 * E, 4096);
        for (int k = 2 * t + 1; k < sample; k += 2 * blockDim.x) acc |= w[k];
#pragma unroll
        for (int d = 16; d; d >>= 1) acc |= __shfl_xor_sync(FULL, acc, d);
        __shared__ unsigned int s[8];
        if ((t & 31) == 0) s[t >> 5] = acc;
        __syncthreads();
        if (t == 0) {
            unsigned int a = 0;
            for (int k = 0; k < 8; k++) a |= s[k];
            g_is64 = (a == 0) ? 1 : 0;
        }
    }
}

__device__ __forceinline__ int edge_at(const void* base, int pos, int N) {
    int v;
    if (g_is64) v = (int)((const long long*)base)[pos];
    else        v = ((const int*)base)[pos];
    return min(max(v, 0), N - 1);
}

__device__ __forceinline__ void edge4(const void* base, int pos, int N, int* out) {
    if (g_is64) {
        longlong2 a = ((const longlong2*)base)[pos >> 1];
        longlong2 b = ((const longlong2*)base)[(pos >> 1) + 1];
        out[0] = (int)a.x; out[1] = (int)a.y; out[2] = (int)b.x; out[3] = (int)b.y;
    } else {
        int4 v = *(const int4*)((const int*)base + pos);
        out[0] = v.x; out[1] = v.y; out[2] = v.z; out[3] = v.w;
    }
#pragma unroll
    for (int k = 0; k < 4; k++) out[k] = min(max(out[k], 0), N - 1);
}

// ---------------- K1: h1 = x @ W1 via wmma (fp16 in, fp32 acc) ----------------
// 256 threads = 8 warps in 4(M)x2(N); block tile 128 nodes x 64 cols; K=128 in 2 chunks.
// smem: [0,18432) xh fp16 128x72 (K-chunk), [18432,36864) wh fp16 128x72 (full K).
// After MMA, fp32 out 128x68 overlays the same buffer.
__global__ void __launch_bounds__(256) k_gemm1(
        const float* __restrict__ x, const float* __restrict__ W1,
        const float* __restrict__ attS, const float* __restrict__ attD, int N) {
    __shared__ __align__(16) char sm[36864];
    __half* xh = (__half*)sm;            // [128][72]
    __half* wh = (__half*)(sm + 18432);  // [128][72] (k rows, 64 cols)
    float* outs = (float*)sm;            // [128][68]

    int t = threadIdx.x;
    int wid = t >> 5;
    int warp_m = wid >> 1, warp_n = wid & 1;
    int n0b = blockIdx.x * 128;
    int row = t >> 1, half = t & 1;      // staging/epilogue mapping

    // stage W1 (128x64) to fp16 once
    {
        const float* src = W1 + row * 64 + half * 32;
#pragma unroll
        for (int q = 0; q < 4; q++) {
            float4 f0 = *(const float4*)(src + q * 8);
            float4 f1 = *(const float4*)(src + q * 8 + 4);
            __half2 p[4] = {__floats2half2_rn(f0.x, f0.y), __floats2half2_rn(f0.z, f0.w),
                            __floats2half2_rn(f1.x, f1.y), __floats2half2_rn(f1.z, f1.w)};
            *(uint4*)(wh + row * 72 + half * 32 + q * 8) = *(uint4*)p;
        }
    }

    wmma::fragment<wmma::accumulator, 16, 16, 16, float> acc[2][2];
#pragma unroll
    for (int mi = 0; mi < 2; mi++)
#pragma unroll
        for (int ni = 0; ni < 2; ni++) wmma::fill_fragment(acc[mi][ni], 0.f);

    for (int chunk = 0; chunk < 2; chunk++) {
        // stage x chunk (128 rows x 64 K-cols) to fp16
        int n = n0b + row;
        const float* src = x + (size_t)n * 128 + chunk * 64 + half * 32;
        bool valid = (n < N);
#pragma unroll
        for (int q = 0; q < 4; q++) {
            float4 f0 = valid ? *(const float4*)(src + q * 8) : make_float4(0.f, 0.f, 0.f, 0.f);
            float4 f1 = valid ? *(const float4*)(src + q * 8 + 4) : make_float4(0.f, 0.f, 0.f, 0.f);
            __half2 p[4] = {__floats2half2_rn(f0.x, f0.y), __floats2half2_rn(f0.z, f0.w),
                            __floats2half2_rn(f1.x, f1.y), __floats2half2_rn(f1.z, f1.w)};
            *(uint4*)(xh + row * 72 + half * 32 + q * 8) = *(uint4*)p;
        }
        __syncthreads();

#pragma unroll
        for (int kk = 0; kk < 4; kk++) {
            wmma::fragment<wmma::matrix_a, 16, 16, 16, __half, wmma::row_major> a0, a1;
            wmma::fragment<wmma::matrix_b, 16, 16, 16, __half, wmma::row_major> b0, b1;
            wmma::load_matrix_sync(a0, xh + (warp_m * 32) * 72 + kk * 16, 72);
            wmma::load_matrix_sync(a1, xh + (warp_m * 32 + 16) * 72 + kk * 16, 72);
            wmma::load_matrix_sync(b0, wh + (chunk * 64 + kk * 16) * 72 + warp_n * 32, 72);
            wmma::load_matrix_sync(b1, wh + (chunk * 64 + kk * 16) * 72 + warp_n * 32 + 16, 72);
            wmma::mma_sync(acc[0][0], a0, b0, acc[0][0]);
            wmma::mma_sync(acc[0][1], a0, b1, acc[0][1]);
            wmma::mma_sync(acc[1][0], a1, b0, acc[1][0]);
            wmma::mma_sync(acc[1][1], a1, b1, acc[1][1]);
        }
        __syncthreads();
    }

    // store accumulators to fp32 smem (overlays xh/wh — all MMA reads done)
#pragma unroll
    for (int mi = 0; mi < 2; mi++)
#pragma unroll
        for (int ni = 0; ni < 2; ni++)
            wmma::store_matrix_sync(outs + (warp_m * 32 + mi * 16) * 68 + warp_n * 32 + ni * 16,
                                    acc[mi][ni], 68, wmma::mem_row_major);
    __syncthreads();

    // epilogue: thread = (row, half): 32 cols = heads 4*half..4*half+3
    {
        int n = n0b + row;
        if (n < N) {
            float v[32];
#pragma unroll
            for (int i = 0; i < 32; i++) v[i] = outs[row * 68 + half * 32 + i];
#pragma unroll
            for (int q = 0; q < 4; q++) {
                int h = 4 * half + q;
                float sa = 0.f, sd = 0.f;
#pragma unroll
                for (int j = 0; j < 8; j++) {
                    sa += v[q * 8 + j] * attS[h * 8 + j];
                    sd += v[q * 8 + j] * attD[h * 8 + j];
                }
                g_asrc1[n * 8 + h] = sa;
                g_adst1[n * 8 + h] = sd;
            }
            __half2 p[4];
#pragma unroll
            for (int q = 0; q < 4; q++) {
#pragma unroll
                for (int r = 0; r < 4; r++)
                    p[r] = __floats2half2_rn(v[q * 8 + 2 * r], v[q * 8 + 2 * r + 1]);
                *(uint4*)(g_h1h + n * 64 + half * 32 + q * 8) = *(uint4*)p;
            }
        }
    }
}

// ---------------- CSR build ----------------
__global__ void k_count(const void* __restrict__ ei, int E, int N) {
    int base = (blockIdx.x * blockDim.x + threadIdx.x) * 4;
    if (base + 3 < E) {
        int d[4];
        edge4(ei, E + base, N, d);
#pragma unroll
        for (int k = 0; k < 4; k++) atomicAdd(&g_deg[d[k]], 1);
    } else {
        for (int e = base; e < E; e++) atomicAdd(&g_deg[edge_at(ei, E + e, N)], 1);
    }
}

__global__ void k_scan1(int N) {
    __shared__ int wsum[8];
    int t = threadIdx.x;
    int base = blockIdx.x * 1024;
    int lane = t & 31, warp = t >> 5;
    int v[4];
    int s = 0;
#pragma unroll
    for (int i = 0; i < 4; i++) {
        int idx = base + t * 4 + i;
        v[i] = (idx < N) ? g_deg[idx] : 0;
        s += v[i];
    }
    int inc = s;
#pragma unroll
    for (int d = 1; d < 32; d <<= 1) {
        int o = __shfl_up_sync(FULL, inc, d);
        if (lane >= d) inc += o;
    }
    if (lane == 31) wsum[warp] = inc;
    __syncthreads();
    if (warp == 0 && lane < 8) {
        int wv = wsum[lane];
        int winc = wv;
#pragma unroll
        for (int d = 1; d < 8; d <<= 1) {
            int o = __shfl_up_sync(0x000000ffu, winc, d);
            if (lane >= d) winc += o;
        }
        wsum[lane] = winc - wv;
        if (lane == 7) g_aux[blockIdx.x] = winc;
    }
    __syncthreads();
    int excl = wsum[warp] + inc - s;
#pragma unroll
    for (int i = 0; i < 4; i++) {
        int idx = base + t * 4 + i;
        if (idx < N) { g_off[idx] = excl; excl += v[i]; }
    }
}

__global__ void k_scan2(int nb) {
    __shared__ int ws[4];
    int t = threadIdx.x;
    int lane = t & 31, warp = t >> 5;
    int v = (t < nb) ? g_aux[t] : 0;
    int inc = v;
#pragma unroll
    for (int d = 1; d < 32; d <<= 1) {
        int o = __shfl_up_sync(FULL, inc, d);
        if (lane >= d) inc += o;
    }
    if (lane == 31) ws[warp] = inc;
    __syncthreads();
    int add = 0;
    for (int w = 0; w < warp; w++) add += ws[w];
    int excl = add + inc - v;
    if (t < nb) g_aux[t] = excl;
}

__global__ void k_scan3(int N) {
    int i = blockIdx.x * blockDim.x + threadIdx.x;
    if (i < N) {
        int o = g_off[i] + g_aux[i >> 10];
        g_off[i] = o;
        g_cur[i] = o;
    }
}

__global__ void k_scatter(const void* __restrict__ ei, int E, int N) {
    int base = (blockIdx.x * blockDim.x + threadIdx.x) * 4;
    if (base + 3 < E) {
        int d[4], sv[4];
        edge4(ei, E + base, N, d);
        edge4(ei, base, N, sv);
#pragma unroll
        for (int k = 0; k < 4; k++) {
            int pos = atomicAdd(&g_cur[d[k]], 1);
            pos = min(max(pos, 0), E - 1);
            g_esrc[pos] = sv[k];
        }
    } else {
        for (int e = base; e < E; e++) {
            int d = edge_at(ei, E + e, N);
            int pos = atomicAdd(&g_cur[d], 1);
            pos = min(max(pos, 0), E - 1);
            g_esrc[pos] = edge_at(ei, e, N);
        }
    }
}

// ---------------- K3: layer-1 aggregation, MLP-4 ----------------
__global__ void k_agg1(const float* __restrict__ b1, int N) {
    __shared__ __align__(16) float sal[8][8 * 36];
    __shared__ float shs[8][8];
    int lane = threadIdx.x & 31;
    int w = threadIdx.x >> 5;
    int node = blockIdx.x * 8 + w;
    if (node >= N) return;
    int start = g_off[node];
    int cnt = g_deg[node] + 1;

    float ad[8];
    {
        float4 d0 = *(const float4*)(g_adst1 + node * 8);
        float4 d1 = *(const float4*)(g_adst1 + node * 8 + 4);
        ad[0] = d0.x; ad[1] = d0.y; ad[2] = d0.z; ad[3] = d0.w;
        ad[4] = d1.x; ad[5] = d1.y; ad[6] = d1.z; ad[7] = d1.w;
    }

    int ha = lane >> 2;
    float accx = 0.f, accy = 0.f;
    float hs[8];
#pragma unroll
    for (int h = 0; h < 8; h++) hs[h] = 0.f;

    for (int base = 0; base < cnt; base += 32) {
        int m = min(32, cnt - base);
        int j = base + lane;
        int mysrc = 0;
        if (lane < m) {
            mysrc = (j == 0) ? node : g_esrc[start + j - 1];
            float4 a0 = *(const float4*)(g_asrc1 + mysrc * 8);
            float4 a1 = *(const float4*)(g_asrc1 + mysrc * 8 + 4);
            float av[8] = {a0.x, a0.y, a0.z, a0.w, a1.x, a1.y, a1.z, a1.w};
#pragma unroll
            for (int h = 0; h < 8; h++) {
                float e = av[h] + ad[h];
                e = (e > 0.f) ? e : 0.2f * e;
                float ex = __expf(e);
                sal[w][h * 36 + lane] = ex;
                hs[h] += ex;
            }
        }
        __syncwarp();
        int jj = 0;
        for (; jj + 4 <= m; jj += 4) {
            int s0 = __shfl_sync(FULL, mysrc, jj);
            int s1 = __shfl_sync(FULL, mysrc, jj + 1);
            int s2 = __shfl_sync(FULL, mysrc, jj + 2);
            int s3 = __shfl_sync(FULL, mysrc, jj + 3);
            float4 pa = *(const float4*)(&sal[w][ha * 36 + jj]);
            float2 f0 = __half22float2(*(const __half2*)(g_h1h + s0 * 64 + 2 * lane));
            float2 f1 = __half22float2(*(const __half2*)(g_h1h + s1 * 64 + 2 * lane));
            float2 f2 = __half22float2(*(const __half2*)(g_h1h + s2 * 64 + 2 * lane));
            float2 f3 = __half22float2(*(const __half2*)(g_h1h + s3 * 64 + 2 * lane));
            accx += pa.x * f0.x + pa.y * f1.x + pa.z * f2.x + pa.w * f3.x;
            accy += pa.x * f0.y + pa.y * f1.y + pa.z * f2.y + pa.w * f3.y;
        }
        for (; jj < m; jj++) {
            int s = __shfl_sync(FULL, mysrc, jj);
            float pa = sal[w][ha * 36 + jj];
            float2 f = __half22float2(*(const __half2*)(g_h1h + s * 64 + 2 * lane));
            accx += pa * f.x;
            accy += pa * f.y;
        }
        __syncwarp();
    }

#pragma unroll
    for (int h = 0; h < 8; h++) {
        float v = hs[h];
#pragma unroll
        for (int d = 16; d; d >>= 1) v += __shfl_xor_sync(FULL, v, d);
        if (lane == 0) shs[w][h] = v;
    }
    __syncwarp();
    float inv = 1.f / shs[w][ha];

    float2 bv = *(const float2*)(b1 + 2 * lane);
    float v0 = accx * inv + bv.x;
    float v1 = accy * inv + bv.y;
    v0 = (v0 > 0.f) ? v0 : (__expf(v0) - 1.f);
    v1 = (v1 > 0.f) ? v1 : (__expf(v1) - 1.f);
    *(float2*)(g_hl1 + node * 64 + 2 * lane) = make_float2(v0, v1);
}

// ---------------- K4: h2 = hl1 @ W2 (+ attention dots) ----------------
__global__ void k_gemm2(const float* __restrict__ W2, const float* __restrict__ attS,
                        const float* __restrict__ attD, int N) {
    __shared__ float xs[128 * 33];
    __shared__ float ws[32 * 40];
    int t = threadIdx.x;
    int cg = t & 7, ng = t >> 3;
    int warp = t >> 5, lane = t & 31;
    int n0b = blockIdx.x * 128;

    float acc[4][5];
#pragma unroll
    for (int i = 0; i < 4; i++)
#pragma unroll
        for (int c = 0; c < 5; c++) acc[i][c] = 0.f;

    for (int kc = 0; kc < 64; kc += 32) {
#pragma unroll
        for (int i = 0; i < 16; i++) {
            int row = warp * 16 + i;
            int n = n0b + row;
            xs[row * 33 + lane] = (n < N) ? g_hl1[n * 64 + kc + lane] : 0.f;
        }
        for (int idx = t; idx < 32 * 40; idx += 256) ws[idx] = W2[kc * 40 + idx];
        __syncthreads();
#pragma unroll
        for (int kk = 0; kk < 32; kk++) {
            float xv[4];
#pragma unroll
            for (int i = 0; i < 4; i++) xv[i] = xs[(ng * 4 + i) * 33 + kk];
            float wv[5];
#pragma unroll
            for (int c = 0; c < 5; c++) wv[c] = ws[kk * 40 + cg * 5 + c];
#pragma unroll
            for (int i = 0; i < 4; i++)
#pragma unroll
                for (int c = 0; c < 5; c++) acc[i][c] += xv[i] * wv[c];
        }
        __syncthreads();
    }

    float as[5], ad[5];
#pragma unroll
    for (int c = 0; c < 5; c++) { as[c] = attS[cg * 5 + c]; ad[c] = attD[cg * 5 + c]; }
#pragma unroll
    for (int i = 0; i < 4; i++) {
        int n = n0b + ng * 4 + i;
        float sa = 0.f, sd = 0.f;
#pragma unroll
        for (int c = 0; c < 5; c++) { sa += acc[i][c] * as[c]; sd += acc[i][c] * ad[c]; }
#pragma unroll
        for (int d = 1; d < 8; d <<= 1) {
            sa += __shfl_xor_sync(FULL, sa, d);
            sd += __shfl_xor_sync(FULL, sd, d);
        }
        if (n < N) {
#pragma unroll
            for (int c = 0; c < 5; c++)
                g_h2h[n * 40 + cg * 5 + c] = __float2half_rn(acc[i][c]);
            if (cg == 0) { g_asrc2[n] = sa; g_adst2[n] = sd; }
        }
    }
}

// ---------------- K5: layer-2 aggregation + log_softmax, MLP-4 ----------------
__global__ void k_agg2(const float* __restrict__ b2, float* __restrict__ out, int N) {
    int lane = threadIdx.x & 31;
    int node = blockIdx.x * 8 + (threadIdx.x >> 5);
    if (node >= N) return;
    int start = g_off[node];
    int cnt = g_deg[node] + 1;
    float adst = g_adst2[node];

    float accx = 0.f, accy = 0.f, ps = 0.f;
    for (int base = 0; base < cnt; base += 32) {
        int m = min(32, cnt - base);
        int j = base + lane;
        int mysrc = 0;
        float myal = 0.f;
        if (lane < m) {
            mysrc = (j == 0) ? node : g_esrc[start + j - 1];
            float e = g_asrc2[mysrc] + adst;
            e = (e > 0.f) ? e : 0.2f * e;
            myal = __expf(e);
            ps += myal;
        }
        int jj = 0;
        for (; jj + 4 <= m; jj += 4) {
            int s0 = __shfl_sync(FULL, mysrc, jj);
            int s1 = __shfl_sync(FULL, mysrc, jj + 1);
            int s2 = __shfl_sync(FULL, mysrc, jj + 2);
            int s3 = __shfl_sync(FULL, mysrc, jj + 3);
            float a0 = __shfl_sync(FULL, myal, jj);
            float a1 = __shfl_sync(FULL, myal, jj + 1);
            float a2 = __shfl_sync(FULL, myal, jj + 2);
            float a3 = __shfl_sync(FULL, myal, jj + 3);
            if (lane < 20) {
                float2 f0 = __half22float2(*(const __half2*)(g_h2h + s0 * 40 + 2 * lane));
                float2 f1 = __half22float2(*(const __half2*)(g_h2h + s1 * 40 + 2 * lane));
                float2 f2 = __half22float2(*(const __half2*)(g_h2h + s2 * 40 + 2 * lane));
                float2 f3 = __half22float2(*(const __half2*)(g_h2h + s3 * 40 + 2 * lane));
                accx += a0 * f0.x + a1 * f1.x + a2 * f2.x + a3 * f3.x;
                accy += a0 * f0.y + a1 * f1.y + a2 * f2.y + a3 * f3.y;
            }
        }
        for (; jj < m; jj++) {
            int s = __shfl_sync(FULL, mysrc, jj);
            float al = __shfl_sync(FULL, myal, jj);
            if (lane < 20) {
                float2 f = __half22float2(*(const __half2*)(g_h2h + s * 40 + 2 * lane));
                accx += al * f.x;
                accy += al * f.y;
            }
        }
    }
#pragma unroll
    for (int d = 16; d; d >>= 1) ps += __shfl_xor_sync(FULL, ps, d);
    float inv = 1.f / ps;

    float v0 = -1e30f, v1 = -1e30f;
    if (lane < 20) {
        v0 = accx * inv + b2[2 * lane];
        v1 = accy * inv + b2[2 * lane + 1];
    }
    float mx = fmaxf(v0, v1);
#pragma unroll
    for (int d = 16; d; d >>= 1) mx = fmaxf(mx, __shfl_xor_sync(FULL, mx, d));
    float se = (lane < 20) ? (__expf(v0 - mx) + __expf(v1 - mx)) : 0.f;
#pragma unroll
    for (int d = 16; d; d >>= 1) se += __shfl_xor_sync(FULL, se, d);
    float ls = __logf(se) + mx;

    if (lane < 20)
        *(float2*)(out + node * 40 + 2 * lane) = make_float2(v0 - ls, v1 - ls);
}

// ---------------- launch ----------------
// NOTE: k_gemm1 is the 4th launch — the profiler captures the 4th launch.
extern "C" void kernel_launch(void* const* d_in, const int* in_sizes, int n_in,
                              void* d_out, int out_size) {
    const float* x   = (const float*)d_in[0];
    const void*  ei  = d_in[1];
    const float* W1  = (const float*)d_in[2];
    const float* aS1 = (const float*)d_in[3];
    const float* aD1 = (const float*)d_in[4];
    const float* b1  = (const float*)d_in[5];
    const float* W2  = (const float*)d_in[6];
    const float* aS2 = (const float*)d_in[7];
    const float* aD2 = (const float*)d_in[8];
    const float* b2  = (const float*)d_in[9];
    float* out = (float*)d_out;

    int N = in_sizes[0] / 128;
    int E = in_sizes[1] / 2;
    int nb1024 = (N + 1023) / 1024;
    int ebq = (E + 1023) / 1024;

    k_zero_detect<<<(N + 255) / 256, 256>>>((const unsigned int*)ei, E, N);
    k_count<<<ebq, 256>>>(ei, E, N);
    k_scan1<<<nb1024, 256>>>(N);
    k_gemm1<<<(N + 127) / 128, 256>>>(x, W1, aS1, aD1, N);   // 4th launch -> profiled
    k_scan2<<<1, 128>>>(nb1024);
    k_scan3<<<(N + 255) / 256, 256>>>(N);
    k_scatter<<<ebq, 256>>>(ei, E, N);
    k_agg1<<<(N + 7) / 8, 256>>>(b1, N);
    k_gemm2<<<(N + 127) / 128, 256>>>(W2, aS2, aD2, N);
    k_agg2<<<(N + 7) / 8, 256>>>(b2, out, N);
}